// round 1
// baseline (speedup 1.0000x reference)
#include <cuda_runtime.h>
#include <cstdint>

// Problem constants
#define BATCH 16
#define CDIM  64
#define HW    4096            // 64*64
#define NROWS 65536           // B*H*W
#define KCODES 512
#define ROWPAD 68             // padded smem row stride (floats) to avoid bank conflicts in gather
#define OUT_ELEMS 4194304     // B*C*H*W
#define LOSS_OFS  4194304
#define PERP_OFS  4194305
#define ACT_OFS   4194306
#define IDX_OFS   4194307

#define MAIN_BLOCKS 128
#define MAIN_THREADS 256
// each block: 512 rows (2 per thread)

__device__ float g_ssq[KCODES];
__device__ int   g_hist[KCODES];
__device__ float g_partial[MAIN_BLOCKS];

typedef unsigned long long ull;

__device__ __forceinline__ ull pack2(float lo, float hi) {
    ull r;
    asm("mov.b64 %0, {%1, %2};" : "=l"(r) : "f"(lo), "f"(hi));
    return r;
}
__device__ __forceinline__ void unpack2(ull v, float& lo, float& hi) {
    asm("mov.b64 {%0, %1}, %2;" : "=f"(lo), "=f"(hi) : "l"(v));
}
__device__ __forceinline__ ull fma2(ull a, ull b, ull c) {
    ull d;
    asm("fma.rn.f32x2 %0, %1, %2, %3;" : "=l"(d) : "l"(a), "l"(b), "l"(c));
    return d;
}
__device__ __forceinline__ ull add2(ull a, ull b) {
    ull d;
    asm("add.rn.f32x2 %0, %1, %2;" : "=l"(d) : "l"(a), "l"(b));
    return d;
}

// ---------------- prep: codebook squared norms + zero histogram ----------------
__global__ void vq_prep(const float* __restrict__ emb) {
    int k = threadIdx.x;
    if (k < KCODES) {
        const float4* e4 = (const float4*)(emb + k * CDIM);
        float s = 0.f;
#pragma unroll
        for (int q = 0; q < CDIM / 4; ++q) {
            float4 v = e4[q];
            s += v.x * v.x + v.y * v.y + v.z * v.z + v.w * v.w;
        }
        g_ssq[k]  = s;
        g_hist[k] = 0;
    }
}

// ---------------- main: distances, argmin, quantized output, hist, commit ----------------
__global__ __launch_bounds__(MAIN_THREADS, 1)
void vq_main(const float* __restrict__ x, const float* __restrict__ emb,
             float* __restrict__ d_out) {
    extern __shared__ float sm[];
    float* se    = sm;                       // [512][68] padded codebook
    float* sssq  = sm + KCODES * ROWPAD;     // [512]
    int*   shist = (int*)(sssq + KCODES);    // [512]
    float* sred  = (float*)(shist + KCODES); // [256]

    const int tid = threadIdx.x;

    // load codebook into padded smem (float4)
    for (int i = tid; i < KCODES * (CDIM / 4); i += MAIN_THREADS) {
        int r = i >> 4, q = i & 15;
        ((float4*)(se + r * ROWPAD))[q] = ((const float4*)emb)[i];
    }
    for (int i = tid; i < KCODES; i += MAIN_THREADS) {
        sssq[i]  = g_ssq[i];
        shist[i] = 0;
    }
    __syncthreads();

    // two rows per thread
    const int r0 = blockIdx.x * 512 + tid;
    const int r1 = r0 + 256;
    const int b0 = r0 >> 12, hw0 = r0 & 4095;
    const int b1 = r1 >> 12, hw1 = r1 & 4095;
    const float* p0 = x + ((long)b0 << 18) + hw0;   // b*64*4096
    const float* p1 = x + ((long)b1 << 18) + hw1;

    ull Xa[32], Xb[32];
#pragma unroll
    for (int j = 0; j < 32; ++j) {
        Xa[j] = pack2(p0[(2 * j) * HW], p0[(2 * j + 1) * HW]);
        Xb[j] = pack2(p1[(2 * j) * HW], p1[(2 * j + 1) * HW]);
    }

    float bestA = 3.4e38f, bestB = 3.4e38f;
    int biA = 0, biB = 0;

    for (int k = 0; k < KCODES; ++k) {
        const ulonglong2* ep = (const ulonglong2*)(se + k * ROWPAD);
        ull a0 = 0, a1 = 0, a2 = 0, a3 = 0;
        ull c0 = 0, c1 = 0, c2 = 0, c3 = 0;
#pragma unroll
        for (int j = 0; j < 16; ++j) {
            ulonglong2 e = ep[j];
            if (j & 1) {
                a2 = fma2(Xa[2 * j], e.x, a2);
                a3 = fma2(Xa[2 * j + 1], e.y, a3);
                c2 = fma2(Xb[2 * j], e.x, c2);
                c3 = fma2(Xb[2 * j + 1], e.y, c3);
            } else {
                a0 = fma2(Xa[2 * j], e.x, a0);
                a1 = fma2(Xa[2 * j + 1], e.y, a1);
                c0 = fma2(Xb[2 * j], e.x, c0);
                c1 = fma2(Xb[2 * j + 1], e.y, c1);
            }
        }
        a0 = add2(add2(a0, a1), add2(a2, a3));
        c0 = add2(add2(c0, c1), add2(c2, c3));
        float alo, ahi, clo, chi;
        unpack2(a0, alo, ahi);
        unpack2(c0, clo, chi);
        const float sq = sssq[k];
        const float sA = fmaf(-2.f, alo + ahi, sq);
        const float sB = fmaf(-2.f, clo + chi, sq);
        if (sA < bestA) { bestA = sA; biA = k; }
        if (sB < bestB) { bestB = sB; biB = k; }
    }

    // epilogue: gather codes, write quantized output, commitment, histogram, indices
    float csum = 0.f;
    {
        float* op = d_out + ((long)b0 << 18) + hw0;
        const float* er = se + biA * ROWPAD;
#pragma unroll
        for (int j = 0; j < 32; ++j) {
            float xl, xh;
            unpack2(Xa[j], xl, xh);
            float e0 = er[2 * j], e1 = er[2 * j + 1];
            float d0 = xl - e0, d1 = xh - e1;
            csum += d0 * d0 + d1 * d1;
            op[(2 * j) * HW]     = e0;
            op[(2 * j + 1) * HW] = e1;
        }
        d_out[IDX_OFS + r0] = (float)biA;
        atomicAdd(&shist[biA], 1);
    }
    {
        float* op = d_out + ((long)b1 << 18) + hw1;
        const float* er = se + biB * ROWPAD;
#pragma unroll
        for (int j = 0; j < 32; ++j) {
            float xl, xh;
            unpack2(Xb[j], xl, xh);
            float e0 = er[2 * j], e1 = er[2 * j + 1];
            float d0 = xl - e0, d1 = xh - e1;
            csum += d0 * d0 + d1 * d1;
            op[(2 * j) * HW]     = e0;
            op[(2 * j + 1) * HW] = e1;
        }
        d_out[IDX_OFS + r1] = (float)biB;
        atomicAdd(&shist[biB], 1);
    }

    // deterministic block reduction of commitment partial
    sred[tid] = csum;
    __syncthreads();
#pragma unroll
    for (int s = 128; s > 0; s >>= 1) {
        if (tid < s) sred[tid] += sred[tid + s];
        __syncthreads();
    }
    if (tid == 0) g_partial[blockIdx.x] = sred[0];

    // merge histogram
    for (int i = tid; i < KCODES; i += MAIN_THREADS) {
        int c = shist[i];
        if (c) atomicAdd(&g_hist[i], c);
    }
}

// ---------------- finalize: perplexity, loss, active codes ----------------
__global__ void vq_finalize(const float* __restrict__ weight, float* __restrict__ d_out) {
    __shared__ float rf[KCODES];
    __shared__ int   ri[KCODES];
    int k = threadIdx.x;
    float p = (float)g_hist[k] * (1.f / (float)NROWS);
    rf[k] = p * logf(p + 1e-10f);
    ri[k] = (weight[k] >= 0.01f) ? 1 : 0;
    __syncthreads();
#pragma unroll
    for (int s = 256; s > 0; s >>= 1) {
        if (k < s) { rf[k] += rf[k + s]; ri[k] += ri[k + s]; }
        __syncthreads();
    }
    if (k == 0) {
        float s = 0.f;
        for (int i = 0; i < MAIN_BLOCKS; ++i) s += g_partial[i];  // fixed order: deterministic
        d_out[LOSS_OFS] = s * (1.f / ((float)NROWS * (float)CDIM));
        d_out[PERP_OFS] = expf(-rf[0]);
        d_out[ACT_OFS]  = (float)ri[0];
    }
}

extern "C" void kernel_launch(void* const* d_in, const int* in_sizes, int n_in,
                              void* d_out, int out_size) {
    const float* x      = (const float*)d_in[0];  // [B,C,H,W]
    const float* emb    = (const float*)d_in[1];  // [K,C]
    const float* weight = (const float*)d_in[2];  // [K]
    float* out = (float*)d_out;

    static bool attr_set = false;
    const int smem = (KCODES * ROWPAD + KCODES + KCODES + MAIN_THREADS) * 4;
    if (!attr_set) {
        cudaFuncSetAttribute(vq_main, cudaFuncAttributeMaxDynamicSharedMemorySize, smem);
        attr_set = true;
    }

    vq_prep<<<1, KCODES>>>(emb);
    vq_main<<<MAIN_BLOCKS, MAIN_THREADS, smem>>>(x, emb, out);
    vq_finalize<<<1, KCODES>>>(weight, out);
}